// round 8
// baseline (speedup 1.0000x reference)
#include <cuda_runtime.h>
#include <cuda_fp16.h>
#include <cstdint>

// ---------------------------------------------------------------------------
// Problem constants (B=8192, N_IN=1024, N=2048)
// ---------------------------------------------------------------------------
#define FN   2048
#define FT   512
#define GM   8192
#define GN   4096
#define GK   1024

// Bank-conflict-free smem swizzle (bijection; XOR bits[4:6) into [0:4))
#define SW(i) ((i) ^ ((((i) >> 4) & 3) * 5))

// Static scratch (no allocs allowed)
__device__ float  g_mul[8192ULL * 4096ULL];   // GEMM output (B, 2N)
__device__ float2 g_z[8192ULL * 2048ULL];     // FFT-pipeline output (B, N) complex
__device__ __half g_Af[8192ULL * 1024ULL];
__device__ __half g_Bf[4096ULL * 1024ULL];

// ---------------------------------------------------------------------------
// fp32 -> fp16 convert
// ---------------------------------------------------------------------------
__global__ void cvt_kernel(const float* __restrict__ src,
                           __half* __restrict__ dst, int n)
{
    int i = blockIdx.x * blockDim.x + threadIdx.x;
    if (i < n) dst[i] = __float2half(src[i]);
}

// ---------------------------------------------------------------------------
// fp16 GEMM:  C[m,n] = sum_k A[m,k]*B[n,k]   (fp32 accumulate)  [unchanged]
// ---------------------------------------------------------------------------
__device__ __forceinline__ void cp_async16(void* smem, const void* gmem)
{
    uint32_t s = (uint32_t)__cvta_generic_to_shared(smem);
    asm volatile("cp.async.cg.shared.global [%0], [%1], 16;\n" :: "r"(s), "l"(gmem));
}

__device__ __forceinline__ void ldsm_x4(uint32_t* r, const void* p)
{
    uint32_t s = (uint32_t)__cvta_generic_to_shared(p);
    asm volatile("ldmatrix.sync.aligned.m8n8.x4.shared.b16 {%0,%1,%2,%3}, [%4];\n"
                 : "=r"(r[0]), "=r"(r[1]), "=r"(r[2]), "=r"(r[3]) : "r"(s));
}

__device__ __forceinline__ void mma16816(float* c, const uint32_t* a, const uint32_t* b)
{
    asm volatile(
        "mma.sync.aligned.m16n8k16.row.col.f32.f16.f16.f32 "
        "{%0,%1,%2,%3}, {%4,%5,%6,%7}, {%8,%9}, {%0,%1,%2,%3};\n"
        : "+f"(c[0]), "+f"(c[1]), "+f"(c[2]), "+f"(c[3])
        : "r"(a[0]), "r"(a[1]), "r"(a[2]), "r"(a[3]), "r"(b[0]), "r"(b[1]));
}

#define SROW 40

__global__ __launch_bounds__(256) void gemm_fp16(
    const __half* __restrict__ Af, const __half* __restrict__ Bf,
    float* __restrict__ C)
{
    __shared__ __half As[2][128 * SROW];
    __shared__ __half Bs[2][128 * SROW];

    const int tid  = threadIdx.x;
    const int wid  = tid >> 5, lane = tid & 31;
    const int wm   = wid >> 1, wn = wid & 1;
    const int bm   = blockIdx.y * 128, bn = blockIdx.x * 128;

    const int NIT = GK / 32;

    float acc[2][8][4];
    #pragma unroll
    for (int mi = 0; mi < 2; ++mi)
        #pragma unroll
        for (int ni = 0; ni < 8; ++ni)
            #pragma unroll
            for (int j = 0; j < 4; ++j) acc[mi][ni][j] = 0.0f;

    auto load_tiles = [&](int st, int it) {
        int kk = it * 32;
        #pragma unroll
        for (int j = 0; j < 2; ++j) {
            int c   = tid + j * 256;
            int row = c >> 2;
            int off = (c & 3) * 8;
            cp_async16(&As[st][row * SROW + off],
                       Af + (size_t)(bm + row) * GK + kk + off);
            cp_async16(&Bs[st][row * SROW + off],
                       Bf + (size_t)(bn + row) * GK + kk + off);
        }
        asm volatile("cp.async.commit_group;\n");
    };

    load_tiles(0, 0);

    for (int it = 0; it < NIT; ++it) {
        int st = it & 1;
        if (it + 1 < NIT) {
            load_tiles(st ^ 1, it + 1);
            asm volatile("cp.async.wait_group 1;\n");
        } else {
            asm volatile("cp.async.wait_group 0;\n");
        }
        __syncthreads();

        #pragma unroll
        for (int ks = 0; ks < 2; ++ks) {
            uint32_t a[2][4], b[8][2];
            int ra = wm * 32 + (lane & 7) + ((lane & 8) ? 8 : 0);
            int ca = ks * 16 + ((lane & 16) ? 8 : 0);
            #pragma unroll
            for (int mi = 0; mi < 2; ++mi)
                ldsm_x4(a[mi], &As[st][(ra + mi * 16) * SROW + ca]);
            int rb = wn * 64 + (lane & 7) + ((lane & 16) ? 8 : 0);
            int cb = ks * 16 + ((lane & 8) ? 8 : 0);
            #pragma unroll
            for (int g = 0; g < 4; ++g) {
                uint32_t r[4];
                ldsm_x4(r, &Bs[st][(rb + g * 16) * SROW + cb]);
                b[2 * g][0] = r[0]; b[2 * g][1] = r[1];
                b[2 * g + 1][0] = r[2]; b[2 * g + 1][1] = r[3];
            }
            #pragma unroll
            for (int mi = 0; mi < 2; ++mi)
                #pragma unroll
                for (int ni = 0; ni < 8; ++ni)
                    mma16816(acc[mi][ni], a[mi], b[ni]);
        }
        __syncthreads();
    }

    #pragma unroll
    for (int mi = 0; mi < 2; ++mi) {
        #pragma unroll
        for (int ni = 0; ni < 8; ++ni) {
            int row = bm + wm * 32 + mi * 16 + (lane >> 2);
            int col = bn + wn * 64 + ni * 8 + (lane & 3) * 2;
            float2* p0 = (float2*)(C + (size_t)row * GN + col);
            float2* p1 = (float2*)(C + (size_t)(row + 8) * GN + col);
            *p0 = make_float2(acc[mi][ni][0], acc[mi][ni][1]);
            *p1 = make_float2(acc[mi][ni][2], acc[mi][ni][3]);
        }
    }
}

// ---------------------------------------------------------------------------
// complex helpers
// ---------------------------------------------------------------------------
__device__ __forceinline__ float2 cmul(float2 a, float2 b)
{
    return make_float2(a.x * b.x - a.y * b.y, a.x * b.y + a.y * b.x);
}
__device__ __forceinline__ float2 cmulc(float2 a, float2 b)   // a * conj(b)
{
    return make_float2(a.x * b.x + a.y * b.y, a.y * b.x - a.x * b.y);
}

// ---------------------------------------------------------------------------
// Reflection dot: returns (fr, fi) with f = 2 <z, conj(v)> / |v|^2.
// ---------------------------------------------------------------------------
__device__ __forceinline__ float2 reflect_factor(
    const float2* z, const float* __restrict__ vre, const float* __restrict__ vim,
    float (*red)[16], int tid)
{
    float sr = 0.f, si = 0.f, sq = 0.f;
    for (int i = tid; i < FN; i += FT) {
        float2 zz = z[SW(i)];
        float vr = vre[i], vi = vim[i];
        sr += zz.x * vr + zz.y * vi;
        si += zz.y * vr - zz.x * vi;
        sq += vr * vr + vi * vi;
    }
    #pragma unroll
    for (int o = 16; o; o >>= 1) {
        sr += __shfl_xor_sync(0xffffffffu, sr, o);
        si += __shfl_xor_sync(0xffffffffu, si, o);
        sq += __shfl_xor_sync(0xffffffffu, sq, o);
    }
    int w = tid >> 5;
    if ((tid & 31) == 0) { red[0][w] = sr; red[1][w] = si; red[2][w] = sq; }
    __syncthreads();
    sr = si = sq = 0.f;
    #pragma unroll
    for (int i = 0; i < 16; ++i) { sr += red[0][i]; si += red[1][i]; sq += red[2][i]; }
    __syncthreads();
    float f = 2.0f / sq;
    return make_float2(f * sr, f * si);
}

// ---------------------------------------------------------------------------
// Phase A: all FFT-pipeline work (no gmul dependency). Writes z to g_z.
// ---------------------------------------------------------------------------
__global__ __launch_bounds__(FT, 3) void urnn_fft_kernel(
    const float* __restrict__ state,
    const float* __restrict__ d1w, const float* __restrict__ r1re, const float* __restrict__ r1im,
    const float* __restrict__ d2w, const float* __restrict__ r2re, const float* __restrict__ r2im,
    const float* __restrict__ d3w, const int* __restrict__ perm,
    float2* __restrict__ gz)
{
    __shared__ float2 bA[FN];
    __shared__ float2 bB[FN];
    __shared__ float2 tw[512];
    __shared__ float  red[3][16];

    const int tid = threadIdx.x;
    const size_t b = blockIdx.x;
    const float* srow = state + b * (2 * FN);
    float2*      zrow = gz    + b * FN;

    for (int i = tid; i < 512; i += FT) {
        float s, c;
        __sincosf(-6.283185307179586f * (float)i / (float)FN, &s, &c);
        tw[i] = make_float2(c, s);
    }
    __syncthreads();

    float2 *x = bA, *y = bB;

    // ---- FWD stage 0 (m=1) fused with global load + diag1 ----
    for (int t = tid; t < 512; t += FT) {
        float2 a0, a1, a2, a3;
        {
            float re, im, s, c;
            re = srow[t];        im = srow[FN + t];        __sincosf(d1w[t], &s, &c);
            a0 = make_float2(c * re - s * im, s * re + c * im);
            re = srow[t + 512];  im = srow[FN + t + 512];  __sincosf(d1w[t + 512], &s, &c);
            a1 = make_float2(c * re - s * im, s * re + c * im);
            re = srow[t + 1024]; im = srow[FN + t + 1024]; __sincosf(d1w[t + 1024], &s, &c);
            a2 = make_float2(c * re - s * im, s * re + c * im);
            re = srow[t + 1536]; im = srow[FN + t + 1536]; __sincosf(d1w[t + 1536], &s, &c);
            a3 = make_float2(c * re - s * im, s * re + c * im);
        }
        float2 w1 = tw[t];
        float2 w2 = cmul(w1, w1);
        float2 w3 = cmul(w2, w1);
        float2 t0 = make_float2(a0.x + a2.x, a0.y + a2.y);
        float2 t1 = make_float2(a0.x - a2.x, a0.y - a2.y);
        float2 t2 = make_float2(a1.x + a3.x, a1.y + a3.y);
        float2 t3 = make_float2(a1.x - a3.x, a1.y - a3.y);
        float2 b0 = make_float2(t0.x + t2.x, t0.y + t2.y);
        float2 b2 = make_float2(t0.x - t2.x, t0.y - t2.y);
        float2 b1 = make_float2(t1.x + t3.y, t1.y - t3.x);
        float2 b3 = make_float2(t1.x - t3.y, t1.y + t3.x);
        int base = 4 * t;
        y[SW(base)]     = b0;
        y[SW(base + 1)] = cmul(w1, b1);
        y[SW(base + 2)] = cmul(w2, b2);
        y[SW(base + 3)] = cmul(w3, b3);
    }
    __syncthreads();
    { float2* tmp = x; x = y; y = tmp; }

    // ---- FWD stages m=4..256 ----
    #pragma unroll
    for (int s = 1; s < 5; ++s) {
        const int m = 1 << (2 * s);
        for (int t = tid; t < 512; t += FT) {
            int pm = t & ~(m - 1);
            float2 a0 = x[SW(t)], a1 = x[SW(t + 512)],
                   a2 = x[SW(t + 1024)], a3 = x[SW(t + 1536)];
            float2 w1 = tw[pm];
            float2 w2 = cmul(w1, w1);
            float2 w3 = cmul(w2, w1);
            float2 t0 = make_float2(a0.x + a2.x, a0.y + a2.y);
            float2 t1 = make_float2(a0.x - a2.x, a0.y - a2.y);
            float2 t2 = make_float2(a1.x + a3.x, a1.y + a3.y);
            float2 t3 = make_float2(a1.x - a3.x, a1.y - a3.y);
            float2 b0 = make_float2(t0.x + t2.x, t0.y + t2.y);
            float2 b2 = make_float2(t0.x - t2.x, t0.y - t2.y);
            float2 b1 = make_float2(t1.x + t3.y, t1.y - t3.x);
            float2 b3 = make_float2(t1.x - t3.y, t1.y + t3.x);
            int base = t + 3 * pm;
            y[SW(base)]         = b0;
            y[SW(base + m)]     = cmul(w1, b1);
            y[SW(base + 2 * m)] = cmul(w2, b2);
            y[SW(base + 3 * m)] = cmul(w3, b3);
        }
        __syncthreads();
        float2* tmp = x; x = y; y = tmp;
    }
    // radix-2 tail
    for (int t = tid; t < 1024; t += FT) {
        float2 c0 = x[SW(t)], c1 = x[SW(t + 1024)];
        y[SW(t)]        = make_float2(c0.x + c1.x, c0.y + c1.y);
        y[SW(t + 1024)] = make_float2(c0.x - c1.x, c0.y - c1.y);
    }
    __syncthreads();
    { float2* tmp = x; x = y; y = tmp; }

    // ---- reflect 1 factors ----
    float2 f1 = reflect_factor(x, r1re, r1im, red, tid);

    // ---- IFFT stage 0 fused with reflect1-update + perm + diag2 ----
    for (int t = tid; t < 512; t += FT) {
        float2 a[4];
        #pragma unroll
        for (int q = 0; q < 4; ++q) {
            int i = t + q * 512;
            int p = perm[i];
            float2 zp = x[SW(p)];
            float vr = r1re[p], vi = r1im[p];
            zp.x -= f1.x * vr - f1.y * vi;
            zp.y -= f1.x * vi + f1.y * vr;
            float s, c; __sincosf(d2w[i], &s, &c);
            a[q] = make_float2(c * zp.x - s * zp.y, s * zp.x + c * zp.y);
        }
        float2 w1 = tw[t];
        float2 w2 = cmul(w1, w1);
        float2 w3 = cmul(w2, w1);
        float2 t0 = make_float2(a[0].x + a[2].x, a[0].y + a[2].y);
        float2 t1 = make_float2(a[0].x - a[2].x, a[0].y - a[2].y);
        float2 t2 = make_float2(a[1].x + a[3].x, a[1].y + a[3].y);
        float2 t3 = make_float2(a[1].x - a[3].x, a[1].y - a[3].y);
        float2 b0 = make_float2(t0.x + t2.x, t0.y + t2.y);
        float2 b2 = make_float2(t0.x - t2.x, t0.y - t2.y);
        float2 b1 = make_float2(t1.x - t3.y, t1.y + t3.x);
        float2 b3 = make_float2(t1.x + t3.y, t1.y - t3.x);
        int base = 4 * t;
        y[SW(base)]     = b0;
        y[SW(base + 1)] = cmulc(b1, w1);
        y[SW(base + 2)] = cmulc(b2, w2);
        y[SW(base + 3)] = cmulc(b3, w3);
    }
    __syncthreads();
    { float2* tmp = x; x = y; y = tmp; }

    // ---- IFFT stages m=4..256 ----
    #pragma unroll
    for (int s = 1; s < 5; ++s) {
        const int m = 1 << (2 * s);
        for (int t = tid; t < 512; t += FT) {
            int pm = t & ~(m - 1);
            float2 a0 = x[SW(t)], a1 = x[SW(t + 512)],
                   a2 = x[SW(t + 1024)], a3 = x[SW(t + 1536)];
            float2 w1 = tw[pm];
            float2 w2 = cmul(w1, w1);
            float2 w3 = cmul(w2, w1);
            float2 t0 = make_float2(a0.x + a2.x, a0.y + a2.y);
            float2 t1 = make_float2(a0.x - a2.x, a0.y - a2.y);
            float2 t2 = make_float2(a1.x + a3.x, a1.y + a3.y);
            float2 t3 = make_float2(a1.x - a3.x, a1.y - a3.y);
            float2 b0 = make_float2(t0.x + t2.x, t0.y + t2.y);
            float2 b2 = make_float2(t0.x - t2.x, t0.y - t2.y);
            float2 b1 = make_float2(t1.x - t3.y, t1.y + t3.x);
            float2 b3 = make_float2(t1.x + t3.y, t1.y - t3.x);
            int base = t + 3 * pm;
            y[SW(base)]         = b0;
            y[SW(base + m)]     = cmulc(b1, w1);
            y[SW(base + 2 * m)] = cmulc(b2, w2);
            y[SW(base + 3 * m)] = cmulc(b3, w3);
        }
        __syncthreads();
        float2* tmp = x; x = y; y = tmp;
    }
    for (int t = tid; t < 1024; t += FT) {
        float2 c0 = x[SW(t)], c1 = x[SW(t + 1024)];
        y[SW(t)]        = make_float2(c0.x + c1.x, c0.y + c1.y);
        y[SW(t + 1024)] = make_float2(c0.x - c1.x, c0.y - c1.y);
    }
    __syncthreads();
    { float2* tmp = x; x = y; y = tmp; }

    // ---- reflect 2 factors ----
    float2 f2 = reflect_factor(x, r2re, r2im, red, tid);

    // ---- final: reflect2-update + diag3*(1/N) -> gz ----
    const float invN = 1.0f / (float)FN;
    for (int i = tid; i < FN; i += FT) {
        float2 zc = x[SW(i)];
        float vr = r2re[i], vi = r2im[i];
        zc.x -= f2.x * vr - f2.y * vi;
        zc.y -= f2.x * vi + f2.y * vr;
        float s, c; __sincosf(d3w[i], &s, &c);
        zrow[i] = make_float2((c * zc.x - s * zc.y) * invN,
                              (s * zc.x + c * zc.y) * invN);
    }
}

// ---------------------------------------------------------------------------
// Join: out = modReLU(gmul + z)   (elementwise, HBM-bound)
// ---------------------------------------------------------------------------
__global__ __launch_bounds__(256) void combine_kernel(
    const float* __restrict__ gmul, const float2* __restrict__ gz,
    const float* __restrict__ b_h, float* __restrict__ out)
{
    int idx = blockIdx.x * blockDim.x + threadIdx.x;      // over GM*FN
    int b = idx >> 11;
    int i = idx & (FN - 1);
    const float* grow = gmul + (size_t)b * (2 * FN);
    float*       orow = out  + (size_t)b * (2 * FN);
    float2 z = gz[idx];
    float pr = grow[i]      + z.x;
    float pi = grow[FN + i] + z.y;
    float norm = sqrtf(pr * pr + pi * pi);
    float sc = fmaxf(norm + b_h[i], 0.0f) / (norm + 1e-6f);
    orow[i]      = pr * sc;
    orow[FN + i] = pi * sc;
}

// ---------------------------------------------------------------------------
// Launch: fork GEMM branch onto a second stream, join before combine.
// ---------------------------------------------------------------------------
extern "C" void kernel_launch(void* const* d_in, const int* in_sizes, int n_in,
                              void* d_out, int out_size)
{
    const float* inputs = (const float*)d_in[0];
    const float* state  = (const float*)d_in[1];
    const float* w_ih   = (const float*)d_in[2];
    const float* b_h    = (const float*)d_in[3];
    const float* d1w    = (const float*)d_in[4];
    const float* r1re   = (const float*)d_in[5];
    const float* r1im   = (const float*)d_in[6];
    const float* d2w    = (const float*)d_in[7];
    const float* r2re   = (const float*)d_in[8];
    const float* r2im   = (const float*)d_in[9];
    const float* d3w    = (const float*)d_in[10];
    const int*   perm   = (const int*)d_in[11];
    float* out = (float*)d_out;

    float *gmul; float2 *gz; __half *Af, *Bf;
    cudaGetSymbolAddress((void**)&gmul, g_mul);
    cudaGetSymbolAddress((void**)&gz,   g_z);
    cudaGetSymbolAddress((void**)&Af, g_Af);
    cudaGetSymbolAddress((void**)&Bf, g_Bf);

    static cudaStream_t s2 = nullptr;
    static cudaEvent_t  eFork = nullptr, eJoin = nullptr;
    if (s2 == nullptr) {
        cudaStreamCreateWithFlags(&s2, cudaStreamNonBlocking);
        cudaEventCreateWithFlags(&eFork, cudaEventDisableTiming);
        cudaEventCreateWithFlags(&eJoin, cudaEventDisableTiming);
    }

    // fork: GEMM branch on s2
    cudaEventRecord(eFork, 0);
    cudaStreamWaitEvent(s2, eFork, 0);

    cvt_kernel<<<(GM * GK) / 256, 256, 0, s2>>>(inputs, Af, GM * GK);
    cvt_kernel<<<(GN * GK) / 256, 256, 0, s2>>>(w_ih,   Bf, GN * GK);
    dim3 ggrid(GN / 128, GM / 128);
    gemm_fp16<<<ggrid, 256, 0, s2>>>(Af, Bf, gmul);
    cudaEventRecord(eJoin, s2);

    // main stream: FFT pipeline (independent of gmul)
    urnn_fft_kernel<<<GM, FT>>>(state,
                                d1w, r1re, r1im,
                                d2w, r2re, r2im,
                                d3w, perm, gz);

    // join, then combine
    cudaStreamWaitEvent(0, eJoin, 0);
    combine_kernel<<<(GM * FN) / 256, 256>>>(gmul, gz, b_h, out);
}

// round 9
// speedup vs baseline: 1.1590x; 1.1590x over previous
#include <cuda_runtime.h>
#include <cuda_fp16.h>
#include <cstdint>

// ---------------------------------------------------------------------------
// Problem constants (B=8192, N_IN=1024, N=2048)
// ---------------------------------------------------------------------------
#define FN   2048
#define FT   512
#define GM   8192
#define GN   4096
#define GK   1024

// Bank-conflict-free smem swizzle (bijection; XOR bits[4:6) into [0:4))
#define SW(i) ((i) ^ ((((i) >> 4) & 3) * 5))

// Static scratch (no allocs allowed)
__device__ float  g_mul[8192ULL * 4096ULL];   // GEMM output (B, 2N)
__device__ __half g_Af[8192ULL * 1024ULL];
__device__ __half g_Bf[4096ULL * 1024ULL];

// ---------------------------------------------------------------------------
// fp32 -> fp16 convert (vectorized)
// ---------------------------------------------------------------------------
__global__ void cvt_kernel(const float4* __restrict__ src,
                           __half* __restrict__ dst, int n4)
{
    int i = blockIdx.x * blockDim.x + threadIdx.x;
    if (i < n4) {
        float4 v = src[i];
        __half2* d = (__half2*)(dst + 4 * (size_t)i);
        d[0] = __floats2half2_rn(v.x, v.y);
        d[1] = __floats2half2_rn(v.z, v.w);
    }
}

// ---------------------------------------------------------------------------
// fp16 GEMM:  C[m,n] = sum_k A[m,k]*B[n,k]   (fp32 accumulate)
// 128x256x32 tiles, 256 thr (8 warps 2x4), mma.sync m16n8k16, cp.async 2-stage
// ---------------------------------------------------------------------------
__device__ __forceinline__ void cp_async16(void* smem, const void* gmem)
{
    uint32_t s = (uint32_t)__cvta_generic_to_shared(smem);
    asm volatile("cp.async.cg.shared.global [%0], [%1], 16;\n" :: "r"(s), "l"(gmem));
}

__device__ __forceinline__ void ldsm_x4(uint32_t* r, const void* p)
{
    uint32_t s = (uint32_t)__cvta_generic_to_shared(p);
    asm volatile("ldmatrix.sync.aligned.m8n8.x4.shared.b16 {%0,%1,%2,%3}, [%4];\n"
                 : "=r"(r[0]), "=r"(r[1]), "=r"(r[2]), "=r"(r[3]) : "r"(s));
}

__device__ __forceinline__ void mma16816(float* c, const uint32_t* a, const uint32_t* b)
{
    asm volatile(
        "mma.sync.aligned.m16n8k16.row.col.f32.f16.f16.f32 "
        "{%0,%1,%2,%3}, {%4,%5,%6,%7}, {%8,%9}, {%0,%1,%2,%3};\n"
        : "+f"(c[0]), "+f"(c[1]), "+f"(c[2]), "+f"(c[3])
        : "r"(a[0]), "r"(a[1]), "r"(a[2]), "r"(a[3]), "r"(b[0]), "r"(b[1]));
}

#define SROW 40
#define GA_H (128 * SROW)            // As per-stage halves
#define GB_H (256 * SROW)            // Bs per-stage halves
#define GEMM_SMEM ((2 * GA_H + 2 * GB_H) * 2)   // 61440 bytes

extern __shared__ char dynsm[];

__global__ __launch_bounds__(256, 1) void gemm_fp16(
    const __half* __restrict__ Af, const __half* __restrict__ Bf,
    float* __restrict__ C)
{
    __half* As = (__half*)dynsm;                    // [2][GA_H]
    __half* Bs = (__half*)dynsm + 2 * GA_H;         // [2][GB_H]

    const int tid  = threadIdx.x;
    const int wid  = tid >> 5, lane = tid & 31;
    const int wm   = wid >> 2, wn = wid & 3;        // warp grid 2(M) x 4(N)
    const int bm   = blockIdx.y * 128, bn = blockIdx.x * 256;

    const int NIT = GK / 32;

    float acc[4][8][4];
    #pragma unroll
    for (int mi = 0; mi < 4; ++mi)
        #pragma unroll
        for (int ni = 0; ni < 8; ++ni)
            #pragma unroll
            for (int j = 0; j < 4; ++j) acc[mi][ni][j] = 0.0f;

    auto load_tiles = [&](int st, int it) {
        int kk = it * 32;
        #pragma unroll
        for (int j = 0; j < 2; ++j) {               // A: 512 chunks
            int c   = tid + j * 256;
            int row = c >> 2;
            int off = (c & 3) * 8;
            cp_async16(&As[st * GA_H + row * SROW + off],
                       Af + (size_t)(bm + row) * GK + kk + off);
        }
        #pragma unroll
        for (int j = 0; j < 4; ++j) {               // B: 1024 chunks
            int c   = tid + j * 256;
            int row = c >> 2;
            int off = (c & 3) * 8;
            cp_async16(&Bs[st * GB_H + row * SROW + off],
                       Bf + (size_t)(bn + row) * GK + kk + off);
        }
        asm volatile("cp.async.commit_group;\n");
    };

    load_tiles(0, 0);

    for (int it = 0; it < NIT; ++it) {
        int st = it & 1;
        if (it + 1 < NIT) {
            load_tiles(st ^ 1, it + 1);
            asm volatile("cp.async.wait_group 1;\n");
        } else {
            asm volatile("cp.async.wait_group 0;\n");
        }
        __syncthreads();

        #pragma unroll
        for (int ks = 0; ks < 2; ++ks) {
            uint32_t a[4][4], b[8][2];
            int ra = wm * 64 + (lane & 7) + ((lane & 8) ? 8 : 0);
            int ca = ks * 16 + ((lane & 16) ? 8 : 0);
            #pragma unroll
            for (int mi = 0; mi < 4; ++mi)
                ldsm_x4(a[mi], &As[st * GA_H + (ra + mi * 16) * SROW + ca]);
            int rb = wn * 64 + (lane & 7) + ((lane & 16) ? 8 : 0);
            int cb = ks * 16 + ((lane & 8) ? 8 : 0);
            #pragma unroll
            for (int g = 0; g < 4; ++g) {
                uint32_t r[4];
                ldsm_x4(r, &Bs[st * GB_H + (rb + g * 16) * SROW + cb]);
                b[2 * g][0] = r[0]; b[2 * g][1] = r[1];
                b[2 * g + 1][0] = r[2]; b[2 * g + 1][1] = r[3];
            }
            #pragma unroll
            for (int mi = 0; mi < 4; ++mi)
                #pragma unroll
                for (int ni = 0; ni < 8; ++ni)
                    mma16816(acc[mi][ni], a[mi], b[ni]);
        }
        __syncthreads();
    }

    #pragma unroll
    for (int mi = 0; mi < 4; ++mi) {
        #pragma unroll
        for (int ni = 0; ni < 8; ++ni) {
            int row = bm + wm * 64 + mi * 16 + (lane >> 2);
            int col = bn + wn * 64 + ni * 8 + (lane & 3) * 2;
            float2* p0 = (float2*)(C + (size_t)row * GN + col);
            float2* p1 = (float2*)(C + (size_t)(row + 8) * GN + col);
            *p0 = make_float2(acc[mi][ni][0], acc[mi][ni][1]);
            *p1 = make_float2(acc[mi][ni][2], acc[mi][ni][3]);
        }
    }
}

// ---------------------------------------------------------------------------
// complex helpers
// ---------------------------------------------------------------------------
__device__ __forceinline__ float2 cmul(float2 a, float2 b)
{
    return make_float2(a.x * b.x - a.y * b.y, a.x * b.y + a.y * b.x);
}
__device__ __forceinline__ float2 cmulc(float2 a, float2 b)   // a * conj(b)
{
    return make_float2(a.x * b.x + a.y * b.y, a.y * b.x - a.x * b.y);
}

// ---------------------------------------------------------------------------
// Block reduction of (sr, si, sq) -> f = 2/sq * (sr, si)
// ---------------------------------------------------------------------------
__device__ __forceinline__ float2 block_reduce_f(
    float sr, float si, float sq, float (*red)[16], int tid)
{
    #pragma unroll
    for (int o = 16; o; o >>= 1) {
        sr += __shfl_xor_sync(0xffffffffu, sr, o);
        si += __shfl_xor_sync(0xffffffffu, si, o);
        sq += __shfl_xor_sync(0xffffffffu, sq, o);
    }
    int w = tid >> 5;
    if ((tid & 31) == 0) { red[0][w] = sr; red[1][w] = si; red[2][w] = sq; }
    __syncthreads();
    sr = si = sq = 0.f;
    #pragma unroll
    for (int i = 0; i < 16; ++i) { sr += red[0][i]; si += red[1][i]; sq += red[2][i]; }
    __syncthreads();
    float f = 2.0f / sq;
    return make_float2(f * sr, f * si);
}

// ---------------------------------------------------------------------------
// Fused URNN pipeline. 1 CTA = 1 row. tw/tw2/tw3 tables, reflect dots fused
// into radix-2 tail stages.
// ---------------------------------------------------------------------------
__global__ __launch_bounds__(FT, 3) void urnn_fused_kernel(
    const float* __restrict__ state, const float* __restrict__ gin,
    const float* __restrict__ b_h,
    const float* __restrict__ d1w, const float* __restrict__ r1re, const float* __restrict__ r1im,
    const float* __restrict__ d2w, const float* __restrict__ r2re, const float* __restrict__ r2im,
    const float* __restrict__ d3w, const int* __restrict__ perm,
    float* __restrict__ out)
{
    __shared__ float2 bA[FN];
    __shared__ float2 bB[FN];
    __shared__ float2 tw1s[512];
    __shared__ float2 tw2s[512];
    __shared__ float2 tw3s[512];
    __shared__ float  red[3][16];

    const int tid = threadIdx.x;
    const size_t b = blockIdx.x;
    const float* srow = state + b * (2 * FN);
    const float* grow = gin   + b * (2 * FN);
    float*       orow = out   + b * (2 * FN);

    for (int i = tid; i < 512; i += FT) {
        float a = -6.283185307179586f * (float)i / (float)FN;
        float s, c;
        __sincosf(a, &s, &c);        tw1s[i] = make_float2(c, s);
        __sincosf(2.f * a, &s, &c);  tw2s[i] = make_float2(c, s);
        __sincosf(3.f * a, &s, &c);  tw3s[i] = make_float2(c, s);
    }
    __syncthreads();

    float2 *x = bA, *y = bB;

    // ---- FWD stage 0 (m=1) fused with global load + diag1 ----
    for (int t = tid; t < 512; t += FT) {
        float2 a0, a1, a2, a3;
        {
            float re, im, s, c;
            re = srow[t];        im = srow[FN + t];        __sincosf(d1w[t], &s, &c);
            a0 = make_float2(c * re - s * im, s * re + c * im);
            re = srow[t + 512];  im = srow[FN + t + 512];  __sincosf(d1w[t + 512], &s, &c);
            a1 = make_float2(c * re - s * im, s * re + c * im);
            re = srow[t + 1024]; im = srow[FN + t + 1024]; __sincosf(d1w[t + 1024], &s, &c);
            a2 = make_float2(c * re - s * im, s * re + c * im);
            re = srow[t + 1536]; im = srow[FN + t + 1536]; __sincosf(d1w[t + 1536], &s, &c);
            a3 = make_float2(c * re - s * im, s * re + c * im);
        }
        float2 t0 = make_float2(a0.x + a2.x, a0.y + a2.y);
        float2 t1 = make_float2(a0.x - a2.x, a0.y - a2.y);
        float2 t2 = make_float2(a1.x + a3.x, a1.y + a3.y);
        float2 t3 = make_float2(a1.x - a3.x, a1.y - a3.y);
        float2 b0 = make_float2(t0.x + t2.x, t0.y + t2.y);
        float2 b2 = make_float2(t0.x - t2.x, t0.y - t2.y);
        float2 b1 = make_float2(t1.x + t3.y, t1.y - t3.x);
        float2 b3 = make_float2(t1.x - t3.y, t1.y + t3.x);
        int base = 4 * t;
        y[SW(base)]     = b0;
        y[SW(base + 1)] = cmul(tw1s[t], b1);
        y[SW(base + 2)] = cmul(tw2s[t], b2);
        y[SW(base + 3)] = cmul(tw3s[t], b3);
    }
    __syncthreads();
    { float2* tmp = x; x = y; y = tmp; }

    // ---- FWD stages m=4..256 ----
    #pragma unroll
    for (int s = 1; s < 5; ++s) {
        const int m = 1 << (2 * s);
        for (int t = tid; t < 512; t += FT) {
            int pm = t & ~(m - 1);
            float2 a0 = x[SW(t)], a1 = x[SW(t + 512)],
                   a2 = x[SW(t + 1024)], a3 = x[SW(t + 1536)];
            float2 t0 = make_float2(a0.x + a2.x, a0.y + a2.y);
            float2 t1 = make_float2(a0.x - a2.x, a0.y - a2.y);
            float2 t2 = make_float2(a1.x + a3.x, a1.y + a3.y);
            float2 t3 = make_float2(a1.x - a3.x, a1.y - a3.y);
            float2 b0 = make_float2(t0.x + t2.x, t0.y + t2.y);
            float2 b2 = make_float2(t0.x - t2.x, t0.y - t2.y);
            float2 b1 = make_float2(t1.x + t3.y, t1.y - t3.x);
            float2 b3 = make_float2(t1.x - t3.y, t1.y + t3.x);
            int base = t + 3 * pm;
            y[SW(base)]         = b0;
            y[SW(base + m)]     = cmul(tw1s[pm], b1);
            y[SW(base + 2 * m)] = cmul(tw2s[pm], b2);
            y[SW(base + 3 * m)] = cmul(tw3s[pm], b3);
        }
        __syncthreads();
        float2* tmp = x; x = y; y = tmp;
    }

    // ---- FWD radix-2 tail fused with reflect-1 dot products ----
    float sr1 = 0.f, si1 = 0.f, sq1 = 0.f;
    for (int t = tid; t < 1024; t += FT) {
        float2 c0 = x[SW(t)], c1 = x[SW(t + 1024)];
        float2 u = make_float2(c0.x + c1.x, c0.y + c1.y);
        float2 v = make_float2(c0.x - c1.x, c0.y - c1.y);
        y[SW(t)]        = u;
        y[SW(t + 1024)] = v;
        float vr = r1re[t], vi = r1im[t];
        sr1 += u.x * vr + u.y * vi;  si1 += u.y * vr - u.x * vi;  sq1 += vr * vr + vi * vi;
        vr = r1re[t + 1024]; vi = r1im[t + 1024];
        sr1 += v.x * vr + v.y * vi;  si1 += v.y * vr - v.x * vi;  sq1 += vr * vr + vi * vi;
    }
    __syncthreads();
    { float2* tmp = x; x = y; y = tmp; }

    float2 f1 = block_reduce_f(sr1, si1, sq1, red, tid);

    // ---- IFFT stage 0 fused with reflect1-update + perm + diag2 ----
    for (int t = tid; t < 512; t += FT) {
        float2 a[4];
        #pragma unroll
        for (int q = 0; q < 4; ++q) {
            int i = t + q * 512;
            int p = perm[i];
            float2 zp = x[SW(p)];
            float vr = r1re[p], vi = r1im[p];
            zp.x -= f1.x * vr - f1.y * vi;
            zp.y -= f1.x * vi + f1.y * vr;
            float s, c; __sincosf(d2w[i], &s, &c);
            a[q] = make_float2(c * zp.x - s * zp.y, s * zp.x + c * zp.y);
        }
        float2 t0 = make_float2(a[0].x + a[2].x, a[0].y + a[2].y);
        float2 t1 = make_float2(a[0].x - a[2].x, a[0].y - a[2].y);
        float2 t2 = make_float2(a[1].x + a[3].x, a[1].y + a[3].y);
        float2 t3 = make_float2(a[1].x - a[3].x, a[1].y - a[3].y);
        float2 b0 = make_float2(t0.x + t2.x, t0.y + t2.y);
        float2 b2 = make_float2(t0.x - t2.x, t0.y - t2.y);
        float2 b1 = make_float2(t1.x - t3.y, t1.y + t3.x);
        float2 b3 = make_float2(t1.x + t3.y, t1.y - t3.x);
        int base = 4 * t;
        y[SW(base)]     = b0;
        y[SW(base + 1)] = cmulc(b1, tw1s[t]);
        y[SW(base + 2)] = cmulc(b2, tw2s[t]);
        y[SW(base + 3)] = cmulc(b3, tw3s[t]);
    }
    __syncthreads();
    { float2* tmp = x; x = y; y = tmp; }

    // ---- IFFT stages m=4..256 ----
    #pragma unroll
    for (int s = 1; s < 5; ++s) {
        const int m = 1 << (2 * s);
        for (int t = tid; t < 512; t += FT) {
            int pm = t & ~(m - 1);
            float2 a0 = x[SW(t)], a1 = x[SW(t + 512)],
                   a2 = x[SW(t + 1024)], a3 = x[SW(t + 1536)];
            float2 t0 = make_float2(a0.x + a2.x, a0.y + a2.y);
            float2 t1 = make_float2(a0.x - a2.x, a0.y - a2.y);
            float2 t2 = make_float2(a1.x + a3.x, a1.y + a3.y);
            float2 t3 = make_float2(a1.x - a3.x, a1.y - a3.y);
            float2 b0 = make_float2(t0.x + t2.x, t0.y + t2.y);
            float2 b2 = make_float2(t0.x - t2.x, t0.y - t2.y);
            float2 b1 = make_float2(t1.x - t3.y, t1.y + t3.x);
            float2 b3 = make_float2(t1.x + t3.y, t1.y - t3.x);
            int base = t + 3 * pm;
            y[SW(base)]         = b0;
            y[SW(base + m)]     = cmulc(b1, tw1s[pm]);
            y[SW(base + 2 * m)] = cmulc(b2, tw2s[pm]);
            y[SW(base + 3 * m)] = cmulc(b3, tw3s[pm]);
        }
        __syncthreads();
        float2* tmp = x; x = y; y = tmp;
    }

    // ---- IFFT radix-2 tail fused with reflect-2 dot products ----
    float sr2 = 0.f, si2 = 0.f, sq2 = 0.f;
    for (int t = tid; t < 1024; t += FT) {
        float2 c0 = x[SW(t)], c1 = x[SW(t + 1024)];
        float2 u = make_float2(c0.x + c1.x, c0.y + c1.y);
        float2 v = make_float2(c0.x - c1.x, c0.y - c1.y);
        y[SW(t)]        = u;
        y[SW(t + 1024)] = v;
        float vr = r2re[t], vi = r2im[t];
        sr2 += u.x * vr + u.y * vi;  si2 += u.y * vr - u.x * vi;  sq2 += vr * vr + vi * vi;
        vr = r2re[t + 1024]; vi = r2im[t + 1024];
        sr2 += v.x * vr + v.y * vi;  si2 += v.y * vr - v.x * vi;  sq2 += vr * vr + vi * vi;
    }
    __syncthreads();
    { float2* tmp = x; x = y; y = tmp; }

    float2 f2 = block_reduce_f(sr2, si2, sq2, red, tid);

    // ---- final: reflect2-update + diag3*(1/N) + add inputs + modReLU ----
    const float invN = 1.0f / (float)FN;
    for (int i = tid; i < FN; i += FT) {
        float2 zc = x[SW(i)];
        float vr = r2re[i], vi = r2im[i];
        zc.x -= f2.x * vr - f2.y * vi;
        zc.y -= f2.x * vi + f2.y * vr;
        float s, c; __sincosf(d3w[i], &s, &c);
        float zr = (c * zc.x - s * zc.y) * invN;
        float zi = (s * zc.x + c * zc.y) * invN;
        float pr = grow[i]      + zr;
        float pi = grow[FN + i] + zi;
        float norm = sqrtf(pr * pr + pi * pi);
        float sc = fmaxf(norm + b_h[i], 0.0f) / (norm + 1e-6f);
        orow[i]      = pr * sc;
        orow[FN + i] = pi * sc;
    }
}

// ---------------------------------------------------------------------------
// Launch (single stream, fused epilogue)
// ---------------------------------------------------------------------------
extern "C" void kernel_launch(void* const* d_in, const int* in_sizes, int n_in,
                              void* d_out, int out_size)
{
    const float* inputs = (const float*)d_in[0];
    const float* state  = (const float*)d_in[1];
    const float* w_ih   = (const float*)d_in[2];
    const float* b_h    = (const float*)d_in[3];
    const float* d1w    = (const float*)d_in[4];
    const float* r1re   = (const float*)d_in[5];
    const float* r1im   = (const float*)d_in[6];
    const float* d2w    = (const float*)d_in[7];
    const float* r2re   = (const float*)d_in[8];
    const float* r2im   = (const float*)d_in[9];
    const float* d3w    = (const float*)d_in[10];
    const int*   perm   = (const int*)d_in[11];
    float* out = (float*)d_out;

    float *gmul; __half *Af, *Bf;
    cudaGetSymbolAddress((void**)&gmul, g_mul);
    cudaGetSymbolAddress((void**)&Af, g_Af);
    cudaGetSymbolAddress((void**)&Bf, g_Bf);

    cvt_kernel<<<(GM * GK / 4) / 256, 256>>>((const float4*)inputs, Af, GM * GK / 4);
    cvt_kernel<<<(GN * GK / 4) / 256, 256>>>((const float4*)w_ih,   Bf, GN * GK / 4);

    static bool attr_set = false;
    if (!attr_set) {
        cudaFuncSetAttribute(gemm_fp16, cudaFuncAttributeMaxDynamicSharedMemorySize,
                             GEMM_SMEM);
        attr_set = true;
    }
    dim3 ggrid(GN / 256, GM / 128);    // 16 x 64
    gemm_fp16<<<ggrid, 256, GEMM_SMEM>>>(Af, Bf, gmul);

    urnn_fused_kernel<<<GM, FT>>>(state, gmul, b_h,
                                  d1w, r1re, r1im,
                                  d2w, r2re, r2im,
                                  d3w, perm, out);
}